// round 9
// baseline (speedup 1.0000x reference)
#include <cuda_runtime.h>
#include <math.h>
#include <stdint.h>

#define BATCH 8
#define CDIM 192
#define C3 576
#define HEADS 8
#define CH 24
#define IMGH 128
#define IMGW 128
#define HW (IMGH * IMGW)

// ---------------- scratch ----------------
__device__ float g_qkv[(size_t)BATCH * C3 * HW];
__device__ float g_v[(size_t)BATCH * CDIM * HW];
__device__ float g_G[BATCH * HEADS * CH * CH];
__device__ float g_nq[BATCH * HEADS * CH];
__device__ float g_nk[BATCH * HEADS * CH];
__device__ float g_M[BATCH * CDIM * CDIM];

// ---------------- helpers ----------------
__device__ __forceinline__ float to_tf32(float x) {
    uint32_t r; asm("cvt.rna.tf32.f32 %0, %1;" : "=r"(r) : "f"(x));
    return __uint_as_float(r);
}
__device__ __forceinline__ uint32_t fu(float x) { return __float_as_uint(x); }

#define MMA_TF32(acc, a, b0r, b1r) \
    asm volatile("mma.sync.aligned.m16n8k8.row.col.f32.tf32.tf32.f32 " \
                 "{%0,%1,%2,%3},{%4,%5,%6,%7},{%8,%9},{%0,%1,%2,%3};" \
                 : "+f"((acc)[0]), "+f"((acc)[1]), "+f"((acc)[2]), "+f"((acc)[3]) \
                 : "r"((a)[0]), "r"((a)[1]), "r"((a)[2]), "r"((a)[3]), \
                   "r"(b0r), "r"(b1r))

// ---------------- K0a/K0b: zero accumulators (split so 4th launch = v-GEMM) ----------------
__global__ void zero_G() {
    int i = blockIdx.x * blockDim.x + threadIdx.x;
    if (i < BATCH * HEADS * CH * CH) g_G[i] = 0.f;
}
__global__ void zero_n() {
    int i = blockIdx.x * blockDim.x + threadIdx.x;
    if (i < BATCH * HEADS * CH) { g_nq[i] = 0.f; g_nk[i] = 0.f; }
}

// ---------------- K1a: q,k rows (0..383) single tf32, double-buffered ----------------
__global__ void __launch_bounds__(256) gemm_qk(const float* __restrict__ W,
                                               const float* __restrict__ x) {
    __shared__ float Ah[2][64 * 20];
    __shared__ float Bh[2][16 * 136];

    int b = blockIdx.z;
    const float* Bb = x + (size_t)b * CDIM * HW;
    float* Cb = g_qkv + (size_t)b * C3 * HW;

    int o0 = blockIdx.y * 64;
    int n0 = blockIdx.x * 128;
    int t = threadIdx.x, lane = t & 31, wid = t >> 5;
    int wm = wid >> 2, wn = wid & 3;

    float acc[2][4][4];
#pragma unroll
    for (int mi = 0; mi < 2; ++mi)
#pragma unroll
        for (int ni = 0; ni < 4; ++ni)
#pragma unroll
            for (int r = 0; r < 4; ++r) acc[mi][ni][r] = 0.f;

    int ar = t >> 2, ac4 = t & 3;
    int bk = t >> 5, bc = t & 31;

    const float* Ap = W + (size_t)(o0 + ar) * CDIM + ac4 * 4;
    float4 avR = *(const float4*)Ap;
    float4 b0R = *(const float4*)(Bb + (size_t)bk * HW + n0 + bc * 4);
    float4 b1R = *(const float4*)(Bb + (size_t)(bk + 8) * HW + n0 + bc * 4);

    for (int kb = 0; kb < 12; ++kb) {
        int buf = kb & 1;
        {
            float* ap = (float*)&avR;
#pragma unroll
            for (int j = 0; j < 4; ++j) Ah[buf][ar * 20 + ac4 * 4 + j] = to_tf32(ap[j]);
            float4 h0, h1;
            float* s0 = (float*)&b0R; float* s1 = (float*)&b1R;
            float* p0 = (float*)&h0;  float* p1 = (float*)&h1;
#pragma unroll
            for (int j = 0; j < 4; ++j) { p0[j] = to_tf32(s0[j]); p1[j] = to_tf32(s1[j]); }
            *(float4*)&Bh[buf][bk * 136 + bc * 4] = h0;
            *(float4*)&Bh[buf][(bk + 8) * 136 + bc * 4] = h1;
        }
        __syncthreads();
        if (kb < 11) {
            int k1 = (kb + 1) * 16;
            avR = *(const float4*)(Ap + k1);
            b0R = *(const float4*)(Bb + (size_t)(k1 + bk) * HW + n0 + bc * 4);
            b1R = *(const float4*)(Bb + (size_t)(k1 + bk + 8) * HW + n0 + bc * 4);
        }
#pragma unroll
        for (int ks = 0; ks < 2; ++ks) {
            int k0 = ks * 8;
            uint32_t ah[2][4];
#pragma unroll
            for (int mi = 0; mi < 2; ++mi) {
                int mr = wm * 32 + mi * 16 + (lane >> 2);
                int kc = k0 + (lane & 3);
                ah[mi][0] = fu(Ah[buf][mr * 20 + kc]);
                ah[mi][1] = fu(Ah[buf][(mr + 8) * 20 + kc]);
                ah[mi][2] = fu(Ah[buf][mr * 20 + kc + 4]);
                ah[mi][3] = fu(Ah[buf][(mr + 8) * 20 + kc + 4]);
            }
#pragma unroll
            for (int ni = 0; ni < 4; ++ni) {
                int bn = wn * 32 + ni * 8 + (lane >> 2);
                int kr = k0 + (lane & 3);
                uint32_t bh0 = fu(Bh[buf][kr * 136 + bn]);
                uint32_t bh1 = fu(Bh[buf][(kr + 4) * 136 + bn]);
#pragma unroll
                for (int mi = 0; mi < 2; ++mi)
                    MMA_TF32(acc[mi][ni], ah[mi], bh0, bh1);
            }
        }
    }

#pragma unroll
    for (int mi = 0; mi < 2; ++mi) {
        int r0 = o0 + wm * 32 + mi * 16 + (lane >> 2);
#pragma unroll
        for (int ni = 0; ni < 4; ++ni) {
            int cc = n0 + wn * 32 + ni * 8 + (lane & 3) * 2;
            *(float2*)(Cb + (size_t)r0 * HW + cc) = make_float2(acc[mi][ni][0], acc[mi][ni][1]);
            *(float2*)(Cb + (size_t)(r0 + 8) * HW + cc) = make_float2(acc[mi][ni][2], acc[mi][ni][3]);
        }
    }
}

// ---------------- K1b / K4: 2-pass (A hi/lo, B hi) tf32 GEMM, double-buffered ----------------
// mode 0: A = W_qkv v-rows, B = x,   C = g_qkv rows 384..575
// mode 1: A = g_M[b],       B = g_v, C = out
__global__ void __launch_bounds__(256) gemm_double(int mode, const float* __restrict__ Aext,
                                                   const float* __restrict__ Bext,
                                                   float* __restrict__ Cext) {
    __shared__ float Ah[2][64 * 20], Al[2][64 * 20];
    __shared__ float Bh[2][16 * 136];

    int b = blockIdx.z;
    const float* Ab = mode ? (g_M + (size_t)b * CDIM * CDIM) : Aext;
    const float* Bb = (mode ? (const float*)g_v : Bext) + (size_t)b * CDIM * HW;
    float* Cb = mode ? (Cext + (size_t)b * CDIM * HW)
                     : (g_qkv + (size_t)b * C3 * HW + (size_t)384 * HW);

    int o0 = blockIdx.y * 64;
    int n0 = blockIdx.x * 128;
    int t = threadIdx.x, lane = t & 31, wid = t >> 5;
    int wm = wid >> 2, wn = wid & 3;

    float acc[2][4][4];
#pragma unroll
    for (int mi = 0; mi < 2; ++mi)
#pragma unroll
        for (int ni = 0; ni < 4; ++ni)
#pragma unroll
            for (int r = 0; r < 4; ++r) acc[mi][ni][r] = 0.f;

    int ar = t >> 2, ac4 = t & 3;
    int bk = t >> 5, bc = t & 31;

    const float* Ap = Ab + (size_t)(o0 + ar) * CDIM + ac4 * 4;
    float4 avR = *(const float4*)Ap;
    float4 b0R = *(const float4*)(Bb + (size_t)bk * HW + n0 + bc * 4);
    float4 b1R = *(const float4*)(Bb + (size_t)(bk + 8) * HW + n0 + bc * 4);

    for (int kb = 0; kb < 12; ++kb) {
        int buf = kb & 1;
        {
            float* ap = (float*)&avR;
#pragma unroll
            for (int j = 0; j < 4; ++j) {
                float hi = to_tf32(ap[j]);
                Ah[buf][ar * 20 + ac4 * 4 + j] = hi;
                Al[buf][ar * 20 + ac4 * 4 + j] = to_tf32(ap[j] - hi);
            }
            float4 h0, h1;
            float* s0 = (float*)&b0R; float* s1 = (float*)&b1R;
            float* p0 = (float*)&h0;  float* p1 = (float*)&h1;
#pragma unroll
            for (int j = 0; j < 4; ++j) { p0[j] = to_tf32(s0[j]); p1[j] = to_tf32(s1[j]); }
            *(float4*)&Bh[buf][bk * 136 + bc * 4] = h0;
            *(float4*)&Bh[buf][(bk + 8) * 136 + bc * 4] = h1;
        }
        __syncthreads();
        if (kb < 11) {
            int k1 = (kb + 1) * 16;
            avR = *(const float4*)(Ap + k1);
            b0R = *(const float4*)(Bb + (size_t)(k1 + bk) * HW + n0 + bc * 4);
            b1R = *(const float4*)(Bb + (size_t)(k1 + bk + 8) * HW + n0 + bc * 4);
        }
#pragma unroll
        for (int ks = 0; ks < 2; ++ks) {
            int k0 = ks * 8;
            uint32_t ah[2][4], al[2][4];
#pragma unroll
            for (int mi = 0; mi < 2; ++mi) {
                int mr = wm * 32 + mi * 16 + (lane >> 2);
                int kc = k0 + (lane & 3);
                ah[mi][0] = fu(Ah[buf][mr * 20 + kc]);
                ah[mi][1] = fu(Ah[buf][(mr + 8) * 20 + kc]);
                ah[mi][2] = fu(Ah[buf][mr * 20 + kc + 4]);
                ah[mi][3] = fu(Ah[buf][(mr + 8) * 20 + kc + 4]);
                al[mi][0] = fu(Al[buf][mr * 20 + kc]);
                al[mi][1] = fu(Al[buf][(mr + 8) * 20 + kc]);
                al[mi][2] = fu(Al[buf][mr * 20 + kc + 4]);
                al[mi][3] = fu(Al[buf][(mr + 8) * 20 + kc + 4]);
            }
#pragma unroll
            for (int ni = 0; ni < 4; ++ni) {
                int bn = wn * 32 + ni * 8 + (lane >> 2);
                int kr = k0 + (lane & 3);
                uint32_t bh0 = fu(Bh[buf][kr * 136 + bn]);
                uint32_t bh1 = fu(Bh[buf][(kr + 4) * 136 + bn]);
#pragma unroll
                for (int mi = 0; mi < 2; ++mi) {
                    MMA_TF32(acc[mi][ni], ah[mi], bh0, bh1);
                    MMA_TF32(acc[mi][ni], al[mi], bh0, bh1);
                }
            }
        }
    }

#pragma unroll
    for (int mi = 0; mi < 2; ++mi) {
        int r0 = o0 + wm * 32 + mi * 16 + (lane >> 2);
#pragma unroll
        for (int ni = 0; ni < 4; ++ni) {
            int cc = n0 + wn * 32 + ni * 8 + (lane & 3) * 2;
            *(float2*)(Cb + (size_t)r0 * HW + cc) = make_float2(acc[mi][ni][0], acc[mi][ni][1]);
            *(float2*)(Cb + (size_t)(r0 + 8) * HW + cc) = make_float2(acc[mi][ni][2], acc[mi][ni][3]);
        }
    }
}

// ---------------- K2: depthwise 3x3 + f-mult + tensor gram + norms + v ----------------
// Div/mod-free staging: 2D thread map, per-thread offsets precomputed once.
// grid: (8, 16, 64), 128 threads (4 warps). Tile 16 wide x 8 tall, halo 18x10.
__global__ void __launch_bounds__(128) k2_dw_gram(const float* __restrict__ feature,
                                                  const float* __restrict__ W_dw) {
    __shared__ float stage[18 * 200];       // 3 planes x 6 ch, each 10x20
    __shared__ float qf_s[128 * 25 + 8];
    __shared__ float kf_s[128 * 25 + 8];
    __shared__ float wdw_s[72 * 9];
    __shared__ float gram_s[CH * CH];

    int bh = blockIdx.z;
    int b = bh >> 3;
    int hd = bh & 7;
    int t = threadIdx.x;
    int lane = t & 31, wid = t >> 5;
    int tx = t & 15, ty = t >> 4;

    for (int i = t; i < 72 * 9; i += 128) {     // init only; div cost negligible
        int c = i / 9, r = i % 9;
        int part = c / 24, cl = c % 24;
        wdw_s[i] = W_dw[(size_t)(part * CDIM + hd * CH + cl) * 9 + r];
    }
    for (int i = t; i < CH * CH; i += 128) gram_s[i] = 0.f;
    qf_s[t * 25 + 24] = 0.f;
    kf_s[t * 25 + 24] = 0.f;

    int x0 = blockIdx.x * 16, y0 = blockIdx.y * 8;
    const size_t img = (size_t)HW;

    // ---- per-thread staging geometry (computed ONCE) ----
    // halo rows: ry0=ty, ry1=ty+8 (ty<2); halo cols: cx0=tx, cx1=tx+16 (tx<2)
    int gy0 = y0 - 1 + ty,      gy1 = y0 + 7 + ty;
    int gx0 = x0 - 1 + tx,      gx1 = x0 + 15 + tx;
    bool r1 = (ty < 2), c1 = (tx < 2);
    bool vy0 = (unsigned)gy0 < IMGH, vy1 = (unsigned)gy1 < IMGH;
    bool vx0 = (unsigned)gx0 < IMGW, vx1 = (unsigned)gx1 < IMGW;
    int o00 = gy0 * IMGW + gx0, o01 = gy0 * IMGW + gx1;
    int o10 = gy1 * IMGW + gx0, o11 = gy1 * IMGW + gx1;
    int s00 = ty * 20 + tx,        s01 = ty * 20 + tx + 16;
    int s10 = (ty + 8) * 20 + tx,  s11 = (ty + 8) * 20 + tx + 16;
    bool p00 = vy0 && vx0, p01 = vy0 && vx1, p10 = vy1 && vx0, p11 = vy1 && vx1;

    const float* qbase = g_qkv + ((size_t)b * C3 + hd * CH) * img;
    const float* fptr = feature + ((size_t)b * CDIM + hd * CH) * img
                        + (size_t)(y0 + ty) * IMGW + x0 + tx;
    float* vptr = g_v + ((size_t)b * CDIM + hd * CH) * img
                  + (size_t)(y0 + ty) * IMGW + x0 + tx;

    for (int r4 = 0; r4 < 4; ++r4) {
        int c0 = r4 * 6;
        __syncthreads();   // protect stage from previous round's readers
        const float* srcc = qbase + (size_t)c0 * img;
#pragma unroll
        for (int p = 0; p < 3; ++p) {
#pragma unroll
            for (int ci = 0; ci < 6; ++ci) {
                const float* src = srcc + (size_t)(p * CDIM + ci) * img;   // const offsets
                float* dst = stage + (p * 6 + ci) * 200;
                dst[s00] = p00 ? src[o00] : 0.f;
                if (c1)       dst[s01] = p01 ? src[o01] : 0.f;
                if (r1)       dst[s10] = p10 ? src[o10] : 0.f;
                if (r1 && c1) dst[s11] = p11 ? src[o11] : 0.f;
            }
        }
        __syncthreads();

        const float* fp = fptr + (size_t)c0 * img;
        float* vp = vptr + (size_t)c0 * img;
#pragma unroll
        for (int ci = 0; ci < 6; ++ci) {
            int c = c0 + ci;
            float q = 0.f, k = 0.f, v = 0.f;
            const float* wq = wdw_s + c * 9;
            const float* wk = wdw_s + (24 + c) * 9;
            const float* wv = wdw_s + (48 + c) * 9;
            const float* sq = stage + ci * 200;
            const float* sk = stage + (6 + ci) * 200;
            const float* sv = stage + (12 + ci) * 200;
#pragma unroll
            for (int ky = 0; ky < 3; ++ky)
#pragma unroll
                for (int kx = 0; kx < 3; ++kx) {
                    int si = (ty + ky) * 20 + tx + kx;
                    q = fmaf(sq[si], wq[ky * 3 + kx], q);
                    k = fmaf(sk[si], wk[ky * 3 + kx], k);
                    v = fmaf(sv[si], wv[ky * 3 + kx], v);
                }
            float f = fp[(size_t)ci * img];
            qf_s[t * 25 + c] = to_tf32(q * f);
            kf_s[t * 25 + c] = to_tf32(k * f);
            vp[(size_t)ci * img] = v;
        }
    }
    __syncthreads();

    // squared-norm partials
    if (t < 48) {
        int c = t % 24;
        const float* src = (t < 24) ? qf_s : kf_s;
        float s = 0.f;
#pragma unroll 4
        for (int p = 0; p < 128; ++p) { float vv = src[p * 25 + c]; s = fmaf(vv, vv, s); }
        atomicAdd(((t < 24) ? g_nq : g_nk) + bh * 24 + c, s);
    }

    // gram via tf32 MMA
    float g[2][3][4];
#pragma unroll
    for (int mi = 0; mi < 2; ++mi)
#pragma unroll
        for (int ni = 0; ni < 3; ++ni)
#pragma unroll
            for (int r = 0; r < 4; ++r) g[mi][ni][r] = 0.f;

#pragma unroll
    for (int ks = 0; ks < 4; ++ks) {
        int pxl = wid * 32 + ks * 8 + (lane & 3);
        uint32_t a[2][4], bb[3][2];
#pragma unroll
        for (int mi = 0; mi < 2; ++mi) {
            int cc = mi * 16 + (lane >> 2);
            a[mi][0] = fu(qf_s[pxl * 25 + cc]);
            a[mi][1] = fu(qf_s[pxl * 25 + cc + 8]);
            a[mi][2] = fu(qf_s[(pxl + 4) * 25 + cc]);
            a[mi][3] = fu(qf_s[(pxl + 4) * 25 + cc + 8]);
        }
#pragma unroll
        for (int ni = 0; ni < 3; ++ni) {
            int dd = ni * 8 + (lane >> 2);
            bb[ni][0] = fu(kf_s[pxl * 25 + dd]);
            bb[ni][1] = fu(kf_s[(pxl + 4) * 25 + dd]);
        }
#pragma unroll
        for (int mi = 0; mi < 2; ++mi)
#pragma unroll
            for (int ni = 0; ni < 3; ++ni)
                MMA_TF32(g[mi][ni], a[mi], bb[ni][0], bb[ni][1]);
    }

#pragma unroll
    for (int mi = 0; mi < 2; ++mi) {
        int r0 = mi * 16 + (lane >> 2);
#pragma unroll
        for (int ni = 0; ni < 3; ++ni) {
            int c0 = ni * 8 + (lane & 3) * 2;
            if (r0 < 24) {
                atomicAdd(&gram_s[r0 * 24 + c0], g[mi][ni][0]);
                atomicAdd(&gram_s[r0 * 24 + c0 + 1], g[mi][ni][1]);
            }
            if (r0 + 8 < 24) {
                atomicAdd(&gram_s[(r0 + 8) * 24 + c0], g[mi][ni][2]);
                atomicAdd(&gram_s[(r0 + 8) * 24 + c0 + 1], g[mi][ni][3]);
            }
        }
    }
    __syncthreads();
    for (int e = t; e < CH * CH; e += 128)
        atomicAdd(&g_G[bh * (CH * CH) + e], gram_s[e]);
}

// ---------------- K3: softmax(attn) + M = W_proj @ blockdiag(attn) ----------------
__global__ void __launch_bounds__(192) k3_attn_M(const float* __restrict__ W_proj,
                                                 const float* __restrict__ temperature) {
    __shared__ float attn_s[24 * 24];
    int bh = blockIdx.x;
    int b = bh >> 3;
    int hd = bh & 7;
    int t = threadIdx.x;

    if (t < 24) {
        float inq = 1.f / fmaxf(sqrtf(g_nq[bh * 24 + t]), 1e-12f);
        float temp = temperature[hd];
        float row[24];
        float mx = -1e30f;
#pragma unroll
        for (int d = 0; d < 24; ++d) {
            float ink = 1.f / fmaxf(sqrtf(g_nk[bh * 24 + d]), 1e-12f);
            float v = g_G[bh * (CH * CH) + t * 24 + d] * inq * ink * temp;
            row[d] = v;
            mx = fmaxf(mx, v);
        }
        float sum = 0.f;
#pragma unroll
        for (int d = 0; d < 24; ++d) { row[d] = expf(row[d] - mx); sum += row[d]; }
        float inv = 1.f / sum;
#pragma unroll
        for (int d = 0; d < 24; ++d) attn_s[t * 24 + d] = row[d] * inv;
    }
    __syncthreads();

    float acc[24];
#pragma unroll
    for (int d = 0; d < 24; ++d) acc[d] = 0.f;
#pragma unroll 1
    for (int cl = 0; cl < 24; ++cl) {
        float w = W_proj[(size_t)t * CDIM + hd * CH + cl];
#pragma unroll
        for (int d = 0; d < 24; ++d) acc[d] = fmaf(w, attn_s[cl * 24 + d], acc[d]);
    }
#pragma unroll
    for (int d = 0; d < 24; ++d)
        g_M[((size_t)b * CDIM + t) * CDIM + hd * CH + d] = acc[d];
}

// ---------------- launch ----------------
// Order: zero_G, zero_n, gemm_qk, gemm_double(v) <- 4th launch = ncu capture, K2, K3, K4.
extern "C" void kernel_launch(void* const* d_in, const int* in_sizes, int n_in,
                              void* d_out, int out_size) {
    const float* x           = (const float*)d_in[0];
    const float* feature     = (const float*)d_in[1];
    const float* W_qkv       = (const float*)d_in[2];
    const float* W_dw        = (const float*)d_in[3];
    const float* W_proj      = (const float*)d_in[4];
    const float* temperature = (const float*)d_in[5];
    float* out = (float*)d_out;

    zero_G<<<144, 256>>>();
    zero_n<<<6, 256>>>();

    // K1a: q,k rows (384 x 16384 per batch), single tf32
    dim3 gqk(HW / 128, 6, BATCH);
    gemm_qk<<<gqk, 256>>>(W_qkv, x);

    // K1b: v rows (192 x 16384 per batch), 2-pass tf32  (4th launch -> ncu capture)
    dim3 gv(HW / 128, 3, BATCH);
    gemm_double<<<gv, 256>>>(0, W_qkv + (size_t)384 * CDIM, x, nullptr);

    // K2: depthwise + gram/norm partials + v
    dim3 g2(IMGW / 16, IMGH / 8, BATCH * HEADS);
    k2_dw_gram<<<g2, 128>>>(feature, W_dw);

    // K3: softmax + fold proj
    k3_attn_M<<<64, 192>>>(W_proj, temperature);

    // K4: out = M @ v (192 x 16384 per batch), 2-pass tf32
    dim3 g4(HW / 128, 3, BATCH);
    gemm_double<<<g4, 256>>>(1, nullptr, nullptr, out);
}

// round 11
// speedup vs baseline: 1.5284x; 1.5284x over previous
#include <cuda_runtime.h>
#include <math.h>
#include <stdint.h>

#define BATCH 8
#define CDIM 192
#define C3 576
#define HEADS 8
#define CH 24
#define IMGH 128
#define IMGW 128
#define HW (IMGH * IMGW)

// ---------------- scratch ----------------
__device__ float g_qkv[(size_t)BATCH * C3 * HW];
__device__ float g_v[(size_t)BATCH * CDIM * HW];
__device__ float g_G[BATCH * HEADS * CH * CH];
__device__ float g_nq[BATCH * HEADS * CH];
__device__ float g_nk[BATCH * HEADS * CH];
__device__ float g_M[BATCH * CDIM * CDIM];

// ---------------- helpers ----------------
__device__ __forceinline__ float to_tf32(float x) {
    uint32_t r; asm("cvt.rna.tf32.f32 %0, %1;" : "=r"(r) : "f"(x));
    return __uint_as_float(r);
}
__device__ __forceinline__ uint32_t fu(float x) { return __float_as_uint(x); }

#define MMA_TF32(acc, a, b0r, b1r) \
    asm volatile("mma.sync.aligned.m16n8k8.row.col.f32.tf32.tf32.f32 " \
                 "{%0,%1,%2,%3},{%4,%5,%6,%7},{%8,%9},{%0,%1,%2,%3};" \
                 : "+f"((acc)[0]), "+f"((acc)[1]), "+f"((acc)[2]), "+f"((acc)[3]) \
                 : "r"((a)[0]), "r"((a)[1]), "r"((a)[2]), "r"((a)[3]), \
                   "r"(b0r), "r"(b1r))

// ---------------- K0a/K0b: zero accumulators ----------------
__global__ void zero_G() {
    int i = blockIdx.x * blockDim.x + threadIdx.x;
    if (i < BATCH * HEADS * CH * CH) g_G[i] = 0.f;
}
__global__ void zero_n() {
    int i = blockIdx.x * blockDim.x + threadIdx.x;
    if (i < BATCH * HEADS * CH) { g_nq[i] = 0.f; g_nk[i] = 0.f; }
}

// ---------------- K1a: q,k rows (0..383) single tf32, double-buffered ----------------
__global__ void __launch_bounds__(256) gemm_qk(const float* __restrict__ W,
                                               const float* __restrict__ x) {
    __shared__ float Ah[2][64 * 20];
    __shared__ float Bh[2][16 * 136];

    int b = blockIdx.z;
    const float* Bb = x + (size_t)b * CDIM * HW;
    float* Cb = g_qkv + (size_t)b * C3 * HW;

    int o0 = blockIdx.y * 64;
    int n0 = blockIdx.x * 128;
    int t = threadIdx.x, lane = t & 31, wid = t >> 5;
    int wm = wid >> 2, wn = wid & 3;

    float acc[2][4][4];
#pragma unroll
    for (int mi = 0; mi < 2; ++mi)
#pragma unroll
        for (int ni = 0; ni < 4; ++ni)
#pragma unroll
            for (int r = 0; r < 4; ++r) acc[mi][ni][r] = 0.f;

    int ar = t >> 2, ac4 = t & 3;
    int bk = t >> 5, bc = t & 31;

    const float* Ap = W + (size_t)(o0 + ar) * CDIM + ac4 * 4;
    float4 avR = *(const float4*)Ap;
    float4 b0R = *(const float4*)(Bb + (size_t)bk * HW + n0 + bc * 4);
    float4 b1R = *(const float4*)(Bb + (size_t)(bk + 8) * HW + n0 + bc * 4);

    for (int kb = 0; kb < 12; ++kb) {
        int buf = kb & 1;
        {
            float* ap = (float*)&avR;
#pragma unroll
            for (int j = 0; j < 4; ++j) Ah[buf][ar * 20 + ac4 * 4 + j] = to_tf32(ap[j]);
            float4 h0, h1;
            float* s0 = (float*)&b0R; float* s1 = (float*)&b1R;
            float* p0 = (float*)&h0;  float* p1 = (float*)&h1;
#pragma unroll
            for (int j = 0; j < 4; ++j) { p0[j] = to_tf32(s0[j]); p1[j] = to_tf32(s1[j]); }
            *(float4*)&Bh[buf][bk * 136 + bc * 4] = h0;
            *(float4*)&Bh[buf][(bk + 8) * 136 + bc * 4] = h1;
        }
        __syncthreads();
        if (kb < 11) {
            int k1 = (kb + 1) * 16;
            avR = *(const float4*)(Ap + k1);
            b0R = *(const float4*)(Bb + (size_t)(k1 + bk) * HW + n0 + bc * 4);
            b1R = *(const float4*)(Bb + (size_t)(k1 + bk + 8) * HW + n0 + bc * 4);
        }
#pragma unroll
        for (int ks = 0; ks < 2; ++ks) {
            int k0 = ks * 8;
            uint32_t ah[2][4];
#pragma unroll
            for (int mi = 0; mi < 2; ++mi) {
                int mr = wm * 32 + mi * 16 + (lane >> 2);
                int kc = k0 + (lane & 3);
                ah[mi][0] = fu(Ah[buf][mr * 20 + kc]);
                ah[mi][1] = fu(Ah[buf][(mr + 8) * 20 + kc]);
                ah[mi][2] = fu(Ah[buf][mr * 20 + kc + 4]);
                ah[mi][3] = fu(Ah[buf][(mr + 8) * 20 + kc + 4]);
            }
#pragma unroll
            for (int ni = 0; ni < 4; ++ni) {
                int bn = wn * 32 + ni * 8 + (lane >> 2);
                int kr = k0 + (lane & 3);
                uint32_t bh0 = fu(Bh[buf][kr * 136 + bn]);
                uint32_t bh1 = fu(Bh[buf][(kr + 4) * 136 + bn]);
#pragma unroll
                for (int mi = 0; mi < 2; ++mi)
                    MMA_TF32(acc[mi][ni], ah[mi], bh0, bh1);
            }
        }
    }

#pragma unroll
    for (int mi = 0; mi < 2; ++mi) {
        int r0 = o0 + wm * 32 + mi * 16 + (lane >> 2);
#pragma unroll
        for (int ni = 0; ni < 4; ++ni) {
            int cc = n0 + wn * 32 + ni * 8 + (lane & 3) * 2;
            *(float2*)(Cb + (size_t)r0 * HW + cc) = make_float2(acc[mi][ni][0], acc[mi][ni][1]);
            *(float2*)(Cb + (size_t)(r0 + 8) * HW + cc) = make_float2(acc[mi][ni][2], acc[mi][ni][3]);
        }
    }
}

// ---------------- K1b / K4: 2-pass (A hi/lo, B hi) tf32 GEMM, double-buffered ----------------
// mode 0: A = W_qkv v-rows, B = x,   C = g_qkv rows 384..575
// mode 1: A = g_M[b],       B = g_v, C = out
__global__ void __launch_bounds__(256) gemm_double(int mode, const float* __restrict__ Aext,
                                                   const float* __restrict__ Bext,
                                                   float* __restrict__ Cext) {
    __shared__ float Ah[2][64 * 20], Al[2][64 * 20];
    __shared__ float Bh[2][16 * 136];

    int b = blockIdx.z;
    const float* Ab = mode ? (g_M + (size_t)b * CDIM * CDIM) : Aext;
    const float* Bb = (mode ? (const float*)g_v : Bext) + (size_t)b * CDIM * HW;
    float* Cb = mode ? (Cext + (size_t)b * CDIM * HW)
                     : (g_qkv + (size_t)b * C3 * HW + (size_t)384 * HW);

    int o0 = blockIdx.y * 64;
    int n0 = blockIdx.x * 128;
    int t = threadIdx.x, lane = t & 31, wid = t >> 5;
    int wm = wid >> 2, wn = wid & 3;

    float acc[2][4][4];
#pragma unroll
    for (int mi = 0; mi < 2; ++mi)
#pragma unroll
        for (int ni = 0; ni < 4; ++ni)
#pragma unroll
            for (int r = 0; r < 4; ++r) acc[mi][ni][r] = 0.f;

    int ar = t >> 2, ac4 = t & 3;
    int bk = t >> 5, bc = t & 31;

    const float* Ap = Ab + (size_t)(o0 + ar) * CDIM + ac4 * 4;
    float4 avR = *(const float4*)Ap;
    float4 b0R = *(const float4*)(Bb + (size_t)bk * HW + n0 + bc * 4);
    float4 b1R = *(const float4*)(Bb + (size_t)(bk + 8) * HW + n0 + bc * 4);

    for (int kb = 0; kb < 12; ++kb) {
        int buf = kb & 1;
        {
            float* ap = (float*)&avR;
#pragma unroll
            for (int j = 0; j < 4; ++j) {
                float hi = to_tf32(ap[j]);
                Ah[buf][ar * 20 + ac4 * 4 + j] = hi;
                Al[buf][ar * 20 + ac4 * 4 + j] = to_tf32(ap[j] - hi);
            }
            float4 h0, h1;
            float* s0 = (float*)&b0R; float* s1 = (float*)&b1R;
            float* p0 = (float*)&h0;  float* p1 = (float*)&h1;
#pragma unroll
            for (int j = 0; j < 4; ++j) { p0[j] = to_tf32(s0[j]); p1[j] = to_tf32(s1[j]); }
            *(float4*)&Bh[buf][bk * 136 + bc * 4] = h0;
            *(float4*)&Bh[buf][(bk + 8) * 136 + bc * 4] = h1;
        }
        __syncthreads();
        if (kb < 11) {
            int k1 = (kb + 1) * 16;
            avR = *(const float4*)(Ap + k1);
            b0R = *(const float4*)(Bb + (size_t)(k1 + bk) * HW + n0 + bc * 4);
            b1R = *(const float4*)(Bb + (size_t)(k1 + bk + 8) * HW + n0 + bc * 4);
        }
#pragma unroll
        for (int ks = 0; ks < 2; ++ks) {
            int k0 = ks * 8;
            uint32_t ah[2][4], al[2][4];
#pragma unroll
            for (int mi = 0; mi < 2; ++mi) {
                int mr = wm * 32 + mi * 16 + (lane >> 2);
                int kc = k0 + (lane & 3);
                ah[mi][0] = fu(Ah[buf][mr * 20 + kc]);
                ah[mi][1] = fu(Ah[buf][(mr + 8) * 20 + kc]);
                ah[mi][2] = fu(Ah[buf][mr * 20 + kc + 4]);
                ah[mi][3] = fu(Ah[buf][(mr + 8) * 20 + kc + 4]);
                al[mi][0] = fu(Al[buf][mr * 20 + kc]);
                al[mi][1] = fu(Al[buf][(mr + 8) * 20 + kc]);
                al[mi][2] = fu(Al[buf][mr * 20 + kc + 4]);
                al[mi][3] = fu(Al[buf][(mr + 8) * 20 + kc + 4]);
            }
#pragma unroll
            for (int ni = 0; ni < 4; ++ni) {
                int bn = wn * 32 + ni * 8 + (lane >> 2);
                int kr = k0 + (lane & 3);
                uint32_t bh0 = fu(Bh[buf][kr * 136 + bn]);
                uint32_t bh1 = fu(Bh[buf][(kr + 4) * 136 + bn]);
#pragma unroll
                for (int mi = 0; mi < 2; ++mi) {
                    MMA_TF32(acc[mi][ni], ah[mi], bh0, bh1);
                    MMA_TF32(acc[mi][ni], al[mi], bh0, bh1);
                }
            }
        }
    }

#pragma unroll
    for (int mi = 0; mi < 2; ++mi) {
        int r0 = o0 + wm * 32 + mi * 16 + (lane >> 2);
#pragma unroll
        for (int ni = 0; ni < 4; ++ni) {
            int cc = n0 + wn * 32 + ni * 8 + (lane & 3) * 2;
            *(float2*)(Cb + (size_t)r0 * HW + cc) = make_float2(acc[mi][ni][0], acc[mi][ni][1]);
            *(float2*)(Cb + (size_t)(r0 + 8) * HW + cc) = make_float2(acc[mi][ni][2], acc[mi][ni][3]);
        }
    }
}

// ---------------- K2: depthwise 3x3 + f-mult + tensor gram + norms + v ----------------
// (EXACT round-8 version — measured 549.9us; round-9 2D rewrite regressed, reverted.)
// 6 channels staged per round (4 rounds, 8 syncs) for high MLP.
// grid: (8, 16, 64), 128 threads (4 warps). Tile 16 wide x 8 tall.
__global__ void __launch_bounds__(128) k2_dw_gram(const float* __restrict__ feature,
                                                  const float* __restrict__ W_dw) {
    __shared__ float stage[3 * 6 * 200];   // [plane][ci][10][20] for 6 channels
    __shared__ float qf_s[128 * 25 + 8];
    __shared__ float kf_s[128 * 25 + 8];
    __shared__ float wdw_s[72 * 9];
    __shared__ float gram_s[CH * CH];

    int bh = blockIdx.z;
    int b = bh >> 3;
    int hd = bh & 7;
    int t = threadIdx.x;
    int lane = t & 31, wid = t >> 5;

    for (int i = t; i < 72 * 9; i += 128) {
        int c = i / 9, r = i % 9;
        int part = c / 24, cl = c % 24;
        wdw_s[i] = W_dw[(size_t)(part * CDIM + hd * CH + cl) * 9 + r];
    }
    for (int i = t; i < CH * CH; i += 128) gram_s[i] = 0.f;
    qf_s[t * 25 + 24] = 0.f;
    kf_s[t * 25 + 24] = 0.f;

    int px = t & 15, py = t >> 4;
    int x0 = blockIdx.x * 16, y0 = blockIdx.y * 8;
    const size_t img = (size_t)HW;

    for (int r = 0; r < 4; ++r) {
        int c0 = r * 6;
        __syncthreads();   // protect stage from previous round's readers
        for (int i = t; i < 3240; i += 128) {
            int p = i / 1080, rem = i % 1080;
            int ci = rem / 180, e = rem % 180;
            int sy = e / 18, sx = e % 18;
            int gy = y0 - 1 + sy, gx = x0 - 1 + sx;
            float v = 0.f;
            if (gy >= 0 && gy < IMGH && gx >= 0 && gx < IMGW)
                v = g_qkv[((size_t)b * C3 + p * CDIM + hd * CH + c0 + ci) * img + gy * IMGW + gx];
            stage[(p * 6 + ci) * 200 + sy * 20 + sx] = v;
        }
        __syncthreads();

#pragma unroll
        for (int ci = 0; ci < 6; ++ci) {
            int c = c0 + ci;
            float q = 0.f, k = 0.f, v = 0.f;
            const float* wq = wdw_s + (0 * 24 + c) * 9;
            const float* wk = wdw_s + (1 * 24 + c) * 9;
            const float* wv = wdw_s + (2 * 24 + c) * 9;
            const float* sq = stage + (0 * 6 + ci) * 200;
            const float* sk = stage + (1 * 6 + ci) * 200;
            const float* sv = stage + (2 * 6 + ci) * 200;
#pragma unroll
            for (int ky = 0; ky < 3; ++ky)
#pragma unroll
                for (int kx = 0; kx < 3; ++kx) {
                    int si = (py + ky) * 20 + px + kx;
                    q = fmaf(sq[si], wq[ky * 3 + kx], q);
                    k = fmaf(sk[si], wk[ky * 3 + kx], k);
                    v = fmaf(sv[si], wv[ky * 3 + kx], v);
                }
            int cq = hd * CH + c;
            float f = feature[((size_t)b * CDIM + cq) * img + (y0 + py) * IMGW + x0 + px];
            qf_s[t * 25 + c] = to_tf32(q * f);
            kf_s[t * 25 + c] = to_tf32(k * f);
            g_v[((size_t)b * CDIM + cq) * img + (y0 + py) * IMGW + x0 + px] = v;
        }
    }
    __syncthreads();

    // squared-norm partials
    if (t < 48) {
        int c = t % 24;
        const float* src = (t < 24) ? qf_s : kf_s;
        float s = 0.f;
#pragma unroll 4
        for (int p = 0; p < 128; ++p) { float vv = src[p * 25 + c]; s = fmaf(vv, vv, s); }
        atomicAdd(((t < 24) ? g_nq : g_nk) + bh * 24 + c, s);
    }

    // gram via tf32 MMA
    float g[2][3][4];
#pragma unroll
    for (int mi = 0; mi < 2; ++mi)
#pragma unroll
        for (int ni = 0; ni < 3; ++ni)
#pragma unroll
            for (int r = 0; r < 4; ++r) g[mi][ni][r] = 0.f;

#pragma unroll
    for (int ks = 0; ks < 4; ++ks) {
        int pxl = wid * 32 + ks * 8 + (lane & 3);
        uint32_t a[2][4], bb[3][2];
#pragma unroll
        for (int mi = 0; mi < 2; ++mi) {
            int cc = mi * 16 + (lane >> 2);
            a[mi][0] = fu(qf_s[pxl * 25 + cc]);
            a[mi][1] = fu(qf_s[pxl * 25 + cc + 8]);
            a[mi][2] = fu(qf_s[(pxl + 4) * 25 + cc]);
            a[mi][3] = fu(qf_s[(pxl + 4) * 25 + cc + 8]);
        }
#pragma unroll
        for (int ni = 0; ni < 3; ++ni) {
            int dd = ni * 8 + (lane >> 2);
            bb[ni][0] = fu(kf_s[pxl * 25 + dd]);
            bb[ni][1] = fu(kf_s[(pxl + 4) * 25 + dd]);
        }
#pragma unroll
        for (int mi = 0; mi < 2; ++mi)
#pragma unroll
            for (int ni = 0; ni < 3; ++ni)
                MMA_TF32(g[mi][ni], a[mi], bb[ni][0], bb[ni][1]);
    }

#pragma unroll
    for (int mi = 0; mi < 2; ++mi) {
        int r0 = mi * 16 + (lane >> 2);
#pragma unroll
        for (int ni = 0; ni < 3; ++ni) {
            int c0 = ni * 8 + (lane & 3) * 2;
            if (r0 < 24) {
                atomicAdd(&gram_s[r0 * 24 + c0], g[mi][ni][0]);
                atomicAdd(&gram_s[r0 * 24 + c0 + 1], g[mi][ni][1]);
            }
            if (r0 + 8 < 24) {
                atomicAdd(&gram_s[(r0 + 8) * 24 + c0], g[mi][ni][2]);
                atomicAdd(&gram_s[(r0 + 8) * 24 + c0 + 1], g[mi][ni][3]);
            }
        }
    }
    __syncthreads();
    for (int e = t; e < CH * CH; e += 128)
        atomicAdd(&g_G[bh * (CH * CH) + e], gram_s[e]);
}

// ---------------- K3: softmax(attn) + M = W_proj @ blockdiag(attn) ----------------
__global__ void __launch_bounds__(192) k3_attn_M(const float* __restrict__ W_proj,
                                                 const float* __restrict__ temperature) {
    __shared__ float attn_s[24 * 24];
    int bh = blockIdx.x;
    int b = bh >> 3;
    int hd = bh & 7;
    int t = threadIdx.x;

    if (t < 24) {
        float inq = 1.f / fmaxf(sqrtf(g_nq[bh * 24 + t]), 1e-12f);
        float temp = temperature[hd];
        float row[24];
        float mx = -1e30f;
#pragma unroll
        for (int d = 0; d < 24; ++d) {
            float ink = 1.f / fmaxf(sqrtf(g_nk[bh * 24 + d]), 1e-12f);
            float v = g_G[bh * (CH * CH) + t * 24 + d] * inq * ink * temp;
            row[d] = v;
            mx = fmaxf(mx, v);
        }
        float sum = 0.f;
#pragma unroll
        for (int d = 0; d < 24; ++d) { row[d] = expf(row[d] - mx); sum += row[d]; }
        float inv = 1.f / sum;
#pragma unroll
        for (int d = 0; d < 24; ++d) attn_s[t * 24 + d] = row[d] * inv;
    }
    __syncthreads();

    float acc[24];
#pragma unroll
    for (int d = 0; d < 24; ++d) acc[d] = 0.f;
#pragma unroll 1
    for (int cl = 0; cl < 24; ++cl) {
        float w = W_proj[(size_t)t * CDIM + hd * CH + cl];
#pragma unroll
        for (int d = 0; d < 24; ++d) acc[d] = fmaf(w, attn_s[cl * 24 + d], acc[d]);
    }
#pragma unroll
    for (int d = 0; d < 24; ++d)
        g_M[((size_t)b * CDIM + t) * CDIM + hd * CH + d] = acc[d];
}

// ---------------- launch ----------------
// Order: zero_G, zero_n, gemm_double(v), gemm_qk <- 4th launch = ncu capture, K2, K3, K4.
// (v-GEMM and qk-GEMM write disjoint row ranges of g_qkv; order between them is free.)
extern "C" void kernel_launch(void* const* d_in, const int* in_sizes, int n_in,
                              void* d_out, int out_size) {
    const float* x           = (const float*)d_in[0];
    const float* feature     = (const float*)d_in[1];
    const float* W_qkv       = (const float*)d_in[2];
    const float* W_dw        = (const float*)d_in[3];
    const float* W_proj      = (const float*)d_in[4];
    const float* temperature = (const float*)d_in[5];
    float* out = (float*)d_out;

    zero_G<<<144, 256>>>();
    zero_n<<<6, 256>>>();

    // K1b: v rows (192 x 16384 per batch), 2-pass tf32
    dim3 gv(HW / 128, 3, BATCH);
    gemm_double<<<gv, 256>>>(0, W_qkv + (size_t)384 * CDIM, x, nullptr);

    // K1a: q,k rows (384 x 16384 per batch), single tf32   (4th launch -> ncu capture)
    dim3 gqk(HW / 128, 6, BATCH);
    gemm_qk<<<gqk, 256>>>(W_qkv, x);

    // K2: depthwise + gram/norm partials + v
    dim3 g2(IMGW / 16, IMGH / 8, BATCH * HEADS);
    k2_dw_gram<<<g2, 128>>>(feature, W_dw);

    // K3: softmax + fold proj
    k3_attn_M<<<64, 192>>>(W_proj, temperature);

    // K4: out = M @ v (192 x 16384 per batch), 2-pass tf32
    dim3 g4(HW / 128, 3, BATCH);
    gemm_double<<<g4, 256>>>(1, nullptr, nullptr, out);
}